// round 5
// baseline (speedup 1.0000x reference)
#include <cuda_runtime.h>
#include <cstdint>

#define BB   16
#define NN   2000
#define CC   20
#define NPAD 2048
#define NW   32
#define NB64 32
#define WIMG 602.0f
#define MINB 5.0f
#define BCT  0.01f
#define CTHR 0.001f
#define IOUT 0.2f
#define MAXWH 4096.0f

__device__ unsigned long long g_keys[BB][NPAD];
__device__ float4             g_sbox[BB][NN];
__device__ float4             g_obox[BB][NN];
__device__ float              g_sarea[BB][NN];
__device__ float              g_sscore[BB][NN];
__device__ int                g_scls[BB][NN];
__device__ int                g_svalid[BB][NN];
__device__ unsigned long long g_mask[BB][NN][NW];
__device__ unsigned long long g_removed[BB][NW];

__device__ __forceinline__ float neg_inf_f() { return __uint_as_float(0xff800000u); }

__device__ __forceinline__ unsigned long long make_key(
    const float* __restrict__ prop, const float* __restrict__ preds,
    const float* __restrict__ bscp, int b, int n)
{
    const float* p = prop + ((size_t)b * NN + n) * 4;
    float x1 = fminf(fmaxf(p[0], 0.f), WIMG);
    float y1 = fminf(fmaxf(p[1], 0.f), WIMG);
    float x2 = fminf(fmaxf(p[2], 0.f), WIMG);
    float y2 = fminf(fmaxf(p[3], 0.f), WIMG);

    const float* pd = preds + ((size_t)b * NN + n) * CC;
    float best = pd[0];
#pragma unroll
    for (int c = 1; c < CC; c++) { float v = pd[c]; if (v > best) best = v; }

    float bsc = bscp[b * NN + n];
    float s = bsc * best;
    bool valid = (bsc > BCT) && ((x2 - x1) >= MINB) && ((y2 - y1) >= MINB) && (s > CTHR);

    float sv = valid ? s : neg_inf_f();
    unsigned u = __float_as_uint(sv);
    u = (u & 0x80000000u) ? ~u : (u | 0x80000000u);
    return ((unsigned long long)u << 32) | (unsigned)(~(unsigned)n);
}

// ---------------- K2: key-gen + bitonic sort (descending) ----------------
__global__ void k2_sort(const float* __restrict__ prop,
                        const float* __restrict__ preds,
                        const float* __restrict__ bscp) {
    __shared__ unsigned long long s[NPAD];
    int b = blockIdx.x;
    int tid = threadIdx.x;                 // 1024 threads
    s[tid] = (tid < NN) ? make_key(prop, preds, bscp, b, tid) : 0ull;
    int t2 = tid + 1024;
    s[t2]  = (t2 < NN) ? make_key(prop, preds, bscp, b, t2) : 0ull;
    __syncthreads();
    for (int k = 2; k <= NPAD; k <<= 1) {
        for (int j = k >> 1; j > 0; j >>= 1) {
#pragma unroll
            for (int off = 0; off < 2; off++) {
                int i = tid + off * 1024;
                int ixj = i ^ j;
                if (ixj > i) {
                    unsigned long long a = s[i], c = s[ixj];
                    bool up = ((i & k) == 0);
                    bool sw = up ? (a < c) : (a > c);
                    if (sw) { s[i] = c; s[ixj] = a; }
                }
            }
            __syncthreads();
        }
    }
    g_keys[b][tid]        = s[tid];
    g_keys[b][tid + 1024] = s[tid + 1024];
}

// ---------------- K3: gather sorted per-proposal data ----------------
__global__ void k3_gather(const float* __restrict__ prop,
                          const float* __restrict__ preds,
                          const float* __restrict__ bscp) {
    int t = blockIdx.x * blockDim.x + threadIdx.x;
    if (t >= BB * NN) return;
    int b = t / NN, ppos = t % NN;
    unsigned long long key = g_keys[b][ppos];
    int n = (int)(~(unsigned)key);

    const float* p = prop + ((size_t)b * NN + n) * 4;
    float x1 = fminf(fmaxf(p[0], 0.f), WIMG);
    float y1 = fminf(fmaxf(p[1], 0.f), WIMG);
    float x2 = fminf(fmaxf(p[2], 0.f), WIMG);
    float y2 = fminf(fmaxf(p[3], 0.f), WIMG);

    const float* pd = preds + ((size_t)b * NN + n) * CC;
    float best = pd[0]; int cid = 0;
#pragma unroll
    for (int c = 1; c < CC; c++) { float v = pd[c]; if (v > best) { best = v; cid = c; } }

    float bsc = bscp[b * NN + n];
    float s = bsc * best;
    bool valid = (bsc > BCT) && ((x2 - x1) >= MINB) && ((y2 - y1) >= MINB) && (s > CTHR);

    float off = (float)cid * MAXWH;
    float ox1 = x1 + off, oy1 = y1 + off, ox2 = x2 + off, oy2 = y2 + off;

    g_sbox[b][ppos]  = make_float4(ox1, oy1, ox2, oy2);
    g_obox[b][ppos]  = make_float4(x1, y1, x2, y2);
    g_sarea[b][ppos] = fmaxf(ox2 - ox1, 0.f) * fmaxf(oy2 - oy1, 0.f);
    g_sscore[b][ppos] = s;
    g_scls[b][ppos]   = cid;
    g_svalid[b][ppos] = valid ? 1 : 0;
}

// ---------------- K4: pairwise IoU mask (upper-triangular, div-free) ----------------
__device__ __forceinline__ unsigned long long iou_bits(
    float4 bi, float ai, const float4* cbx, const float* car, int jlo, int jmax)
{
    unsigned long long m = 0ull;
#pragma unroll 4
    for (int jj = jlo; jj < jmax; jj++) {
        float4 bj = cbx[jj];
        float lx = fmaxf(bi.x, bj.x), ly = fmaxf(bi.y, bj.y);
        float rx = fminf(bi.z, bj.z), ry = fminf(bi.w, bj.w);
        float w = fmaxf(rx - lx, 0.f), h = fmaxf(ry - ly, 0.f);
        float inter = w * h;
        float uni = fmaxf(ai + car[jj] - inter, 1e-9f);
        if (fmaf(-IOUT, uni, inter) > 0.f) m |= (1ull << jj);  // iou>thr, no div
    }
    return m;
}

__global__ void k4_mask() {
    int b  = blockIdx.z;
    int rb = blockIdx.y;
    int cb = blockIdx.x;
    if (cb < rb) return;
    __shared__ float4 cbx[64];
    __shared__ float  car[64];
    int j = cb * 64 + threadIdx.x;
    if (j < NN) { cbx[threadIdx.x] = g_sbox[b][j]; car[threadIdx.x] = g_sarea[b][j]; }
    else        { cbx[threadIdx.x] = make_float4(0.f,0.f,0.f,0.f); car[threadIdx.x] = 0.f; }
    __syncthreads();

    int i = rb * 64 + threadIdx.x;
    if (i >= NN) return;
    float4 bi = g_sbox[b][i];
    float  ai = g_sarea[b][i];
    int jmax = min(64, NN - cb * 64);
    unsigned long long m;
    if (cb == rb) m = iou_bits(bi, ai, cbx, car, threadIdx.x + 1, jmax);
    else          m = iou_bits(bi, ai, cbx, car, 0, jmax);
    g_mask[b][i][cb] = m;
}

// ---------------- K5: greedy scan — SMEM-staged rows, 2-register chain ----------------
// Per 64-chunk: stage the 64 diagonal row-words in SMEM (broadcast reads are
// off the serial chain), then resolve with a pure-register recurrence:
//   notS &= ~(w_bb & broadcast(bit bb of notS))
// (SHL-const + SHR-arith bit broadcast + LOP3; ~12 cyc/step). Final notS = alive set.
__global__ void __launch_bounds__(32) k5_reduce() {
    const unsigned FULL = 0xffffffffu;
    __shared__ unsigned long long rows[64];
    int img = blockIdx.x;
    int lane = threadIdx.x;
    unsigned long long rem = 0ull;

    // preload chunk 0 inputs
    int pi0 = lane, pi1 = 32 + lane;
    unsigned long long nd0 = g_mask[img][pi0][0];
    unsigned long long nd1 = g_mask[img][pi1][0];
    int nv0 = g_svalid[img][pi0];
    int nv1 = g_svalid[img][pi1];

    for (int chunk = 0; chunk < NW; chunk++) {
        int base = chunk * 64;
        unsigned long long d0 = nd0, d1 = nd1;
        int v0 = nv0, v1 = nv1;

        rows[lane]      = d0;
        rows[lane + 32] = d1;
        __syncwarp();

        unsigned long long cur0 = __shfl_sync(FULL, rem, chunk);
        unsigned lo = __ballot_sync(FULL, v0 != 0);
        unsigned hi = __ballot_sync(FULL, v1 != 0);
        unsigned long long notS = ((((unsigned long long)hi << 32) | lo)) & ~cur0;

        // serial resolve: fully unrolled, constants everywhere
#pragma unroll
        for (int bb = 0; bb < 64; bb++) {
            unsigned long long w = rows[bb];          // LDS broadcast, off-chain
            unsigned half = (bb < 32) ? (unsigned)notS : (unsigned)(notS >> 32);
            int msk = ((int)(half << (31 - (bb & 31)))) >> 31;   // bit bb -> all 64 bits
            unsigned long long mm = (unsigned long long)(long long)msk;
            notS &= ~(w & mm);                        // LOP3 per half
        }
        // notS == alive set (suppression only ever clears bits with index > bb)

        // prefetch next chunk inputs while apply loads are in flight
        if (chunk + 1 < NW) {
            int b2 = base + 64;
            int i0 = b2 + lane, i1 = b2 + 32 + lane;
            nd0 = (i0 < NN) ? g_mask[img][i0][chunk + 1] : 0ull;
            nd1 = (i1 < NN) ? g_mask[img][i1][chunk + 1] : 0ull;
            nv0 = (i0 < NN) ? g_svalid[img][i0] : 0;
            nv1 = (i1 < NN) ? g_svalid[img][i1] : 0;
        }

        // apply: OR alive rows' mask words into rem (independent L2 loads).
        // lane < chunk words are structurally zero (never written) -> skip.
        if (lane >= chunk) {
            unsigned long long t = notS;
            while (t) {
                int bb = __ffsll((long long)t) - 1;
                t &= t - 1;
                rem |= g_mask[img][base + bb][lane];
            }
        }
        __syncwarp();   // rows[] reuse guard
    }
    g_removed[img][lane] = rem;
}

// ---------------- K6: write [B,N,6] output ----------------
__global__ void k6_out(float* __restrict__ out) {
    int t = blockIdx.x * blockDim.x + threadIdx.x;
    if (t >= BB * NN) return;
    int b = t / NN, p = t % NN;
    unsigned long long w = g_removed[b][p >> 6];
    bool rem = (w >> (p & 63)) & 1ull;
    bool keep = g_svalid[b][p] && !rem;
    float* o = out + ((size_t)b * NN + p) * 6;
    if (keep) {
        float4 bx = g_obox[b][p];
        o[0] = bx.x; o[1] = bx.y; o[2] = bx.z; o[3] = bx.w;
        o[4] = g_sscore[b][p];
        o[5] = (float)g_scls[b][p];
    } else {
        o[0] = 0.f; o[1] = 0.f; o[2] = 0.f; o[3] = 0.f; o[4] = 0.f; o[5] = 0.f;
    }
}

extern "C" void kernel_launch(void* const* d_in, const int* in_sizes, int n_in,
                              void* d_out, int out_size) {
    const float* prop  = (const float*)d_in[0];
    const float* preds = (const float*)d_in[1];
    const float* bsc   = (const float*)d_in[2];
    float* out = (float*)d_out;

    (void)in_sizes; (void)n_in; (void)out_size;

    k2_sort<<<BB, 1024>>>(prop, preds, bsc);
    int tot2 = BB * NN;
    k3_gather<<<(tot2 + 255) / 256, 256>>>(prop, preds, bsc);
    dim3 mg(NB64, NB64, BB);
    k4_mask<<<mg, 64>>>();
    k5_reduce<<<BB, 32>>>();
    k6_out<<<(tot2 + 255) / 256, 256>>>(out);
}

// round 6
// speedup vs baseline: 1.8692x; 1.8692x over previous
#include <cuda_runtime.h>
#include <cstdint>

#define BB   16
#define NN   2000
#define CC   20
#define NPAD 2048
#define NW   32
#define NB64 32
#define WIMG 602.0f
#define MINB 5.0f
#define BCT  0.01f
#define CTHR 0.001f
#define IOUT 0.2f
#define MAXWH 4096.0f

__device__ unsigned long long g_keys[BB][NPAD];
__device__ float4             g_sbox[BB][NN];
__device__ float4             g_obox[BB][NN];
__device__ float              g_sarea[BB][NN];
__device__ float              g_sscore[BB][NN];
__device__ int                g_scls[BB][NN];
__device__ int                g_svalid[BB][NN];
__device__ unsigned long long g_mask[BB][NN][NW];
__device__ unsigned long long g_removed[BB][NW];

__device__ __forceinline__ float neg_inf_f() { return __uint_as_float(0xff800000u); }

__device__ __forceinline__ unsigned long long make_key(
    const float* __restrict__ prop, const float* __restrict__ preds,
    const float* __restrict__ bscp, int b, int n)
{
    const float* p = prop + ((size_t)b * NN + n) * 4;
    float x1 = fminf(fmaxf(p[0], 0.f), WIMG);
    float y1 = fminf(fmaxf(p[1], 0.f), WIMG);
    float x2 = fminf(fmaxf(p[2], 0.f), WIMG);
    float y2 = fminf(fmaxf(p[3], 0.f), WIMG);

    const float* pd = preds + ((size_t)b * NN + n) * CC;
    float best = pd[0];
#pragma unroll
    for (int c = 1; c < CC; c++) { float v = pd[c]; if (v > best) best = v; }

    float bsc = bscp[b * NN + n];
    float s = bsc * best;
    bool valid = (bsc > BCT) && ((x2 - x1) >= MINB) && ((y2 - y1) >= MINB) && (s > CTHR);

    float sv = valid ? s : neg_inf_f();
    unsigned u = __float_as_uint(sv);
    u = (u & 0x80000000u) ? ~u : (u | 0x80000000u);
    return ((unsigned long long)u << 32) | (unsigned)(~(unsigned)n);
}

// ---------------- K2: key-gen + bitonic sort (descending) ----------------
__global__ void k2_sort(const float* __restrict__ prop,
                        const float* __restrict__ preds,
                        const float* __restrict__ bscp) {
    __shared__ unsigned long long s[NPAD];
    int b = blockIdx.x;
    int tid = threadIdx.x;                 // 1024 threads
    s[tid] = (tid < NN) ? make_key(prop, preds, bscp, b, tid) : 0ull;
    int t2 = tid + 1024;
    s[t2]  = (t2 < NN) ? make_key(prop, preds, bscp, b, t2) : 0ull;
    __syncthreads();
    for (int k = 2; k <= NPAD; k <<= 1) {
        for (int j = k >> 1; j > 0; j >>= 1) {
#pragma unroll
            for (int off = 0; off < 2; off++) {
                int i = tid + off * 1024;
                int ixj = i ^ j;
                if (ixj > i) {
                    unsigned long long a = s[i], c = s[ixj];
                    bool up = ((i & k) == 0);
                    bool sw = up ? (a < c) : (a > c);
                    if (sw) { s[i] = c; s[ixj] = a; }
                }
            }
            __syncthreads();
        }
    }
    g_keys[b][tid]        = s[tid];
    g_keys[b][tid + 1024] = s[tid + 1024];
}

// ---------------- K3: gather sorted per-proposal data ----------------
__global__ void k3_gather(const float* __restrict__ prop,
                          const float* __restrict__ preds,
                          const float* __restrict__ bscp) {
    int t = blockIdx.x * blockDim.x + threadIdx.x;
    if (t >= BB * NN) return;
    int b = t / NN, ppos = t % NN;
    unsigned long long key = g_keys[b][ppos];
    int n = (int)(~(unsigned)key);

    const float* p = prop + ((size_t)b * NN + n) * 4;
    float x1 = fminf(fmaxf(p[0], 0.f), WIMG);
    float y1 = fminf(fmaxf(p[1], 0.f), WIMG);
    float x2 = fminf(fmaxf(p[2], 0.f), WIMG);
    float y2 = fminf(fmaxf(p[3], 0.f), WIMG);

    const float* pd = preds + ((size_t)b * NN + n) * CC;
    float best = pd[0]; int cid = 0;
#pragma unroll
    for (int c = 1; c < CC; c++) { float v = pd[c]; if (v > best) { best = v; cid = c; } }

    float bsc = bscp[b * NN + n];
    float s = bsc * best;
    bool valid = (bsc > BCT) && ((x2 - x1) >= MINB) && ((y2 - y1) >= MINB) && (s > CTHR);

    float off = (float)cid * MAXWH;
    float ox1 = x1 + off, oy1 = y1 + off, ox2 = x2 + off, oy2 = y2 + off;

    g_sbox[b][ppos]  = make_float4(ox1, oy1, ox2, oy2);
    g_obox[b][ppos]  = make_float4(x1, y1, x2, y2);
    g_sarea[b][ppos] = fmaxf(ox2 - ox1, 0.f) * fmaxf(oy2 - oy1, 0.f);
    g_sscore[b][ppos] = s;
    g_scls[b][ppos]   = cid;
    g_svalid[b][ppos] = valid ? 1 : 0;
}

// ---------------- K4: pairwise IoU mask (upper-triangular, div-free) ----------------
__device__ __forceinline__ unsigned long long iou_bits(
    float4 bi, float ai, const float4* cbx, const float* car, int jlo, int jmax)
{
    unsigned long long m = 0ull;
#pragma unroll 4
    for (int jj = jlo; jj < jmax; jj++) {
        float4 bj = cbx[jj];
        float lx = fmaxf(bi.x, bj.x), ly = fmaxf(bi.y, bj.y);
        float rx = fminf(bi.z, bj.z), ry = fminf(bi.w, bj.w);
        float w = fmaxf(rx - lx, 0.f), h = fmaxf(ry - ly, 0.f);
        float inter = w * h;
        float uni = fmaxf(ai + car[jj] - inter, 1e-9f);
        if (fmaf(-IOUT, uni, inter) > 0.f) m |= (1ull << jj);  // iou>thr, no div
    }
    return m;
}

__global__ void k4_mask() {
    int b  = blockIdx.z;
    int rb = blockIdx.y;
    int cb = blockIdx.x;
    if (cb < rb) return;
    __shared__ float4 cbx[64];
    __shared__ float  car[64];
    int j = cb * 64 + threadIdx.x;
    if (j < NN) { cbx[threadIdx.x] = g_sbox[b][j]; car[threadIdx.x] = g_sarea[b][j]; }
    else        { cbx[threadIdx.x] = make_float4(0.f,0.f,0.f,0.f); car[threadIdx.x] = 0.f; }
    __syncthreads();

    int i = rb * 64 + threadIdx.x;
    if (i >= NN) return;
    float4 bi = g_sbox[b][i];
    float  ai = g_sarea[b][i];
    int jmax = min(64, NN - cb * 64);
    unsigned long long m;
    if (cb == rb) m = iou_bits(bi, ai, cbx, car, threadIdx.x + 1, jmax);
    else          m = iou_bits(bi, ai, cbx, car, 0, jmax);
    g_mask[b][i][cb] = m;
}

// ---------------- K5: greedy scan — register chain + high-MLP unrolled apply ----------------
__global__ void __launch_bounds__(32) k5_reduce() {
    const unsigned FULL = 0xffffffffu;
    __shared__ unsigned long long rows[64];
    int img = blockIdx.x;
    int lane = threadIdx.x;
    unsigned long long rem = 0ull;

    // preload chunk 0 inputs
    unsigned long long nd0 = g_mask[img][lane][0];
    unsigned long long nd1 = g_mask[img][32 + lane][0];
    int nv0 = g_svalid[img][lane];
    int nv1 = g_svalid[img][32 + lane];

    for (int chunk = 0; chunk < NW; chunk++) {
        int base = chunk * 64;

        rows[lane]      = nd0;
        rows[lane + 32] = nd1;
        int v0 = nv0, v1 = nv1;
        __syncwarp();

        unsigned long long cur0 = __shfl_sync(FULL, rem, chunk);
        unsigned lo = __ballot_sync(FULL, v0 != 0);
        unsigned hi = __ballot_sync(FULL, v1 != 0);
        unsigned long long notS = ((((unsigned long long)hi << 32) | lo)) & ~cur0;

        // serial resolve: groups of 8 explicit LDS (8 in flight), chain = shifts+LOP3
#pragma unroll
        for (int g = 0; g < 64; g += 8) {
            unsigned long long w0 = rows[g + 0], w1 = rows[g + 1];
            unsigned long long w2 = rows[g + 2], w3 = rows[g + 3];
            unsigned long long w4 = rows[g + 4], w5 = rows[g + 5];
            unsigned long long w6 = rows[g + 6], w7 = rows[g + 7];
#define STEP(WREG, BBC)                                                          \
            {                                                                    \
                const int bbq = (BBC);                                           \
                unsigned half = (bbq < 32) ? (unsigned)notS                      \
                                           : (unsigned)(notS >> 32);             \
                int mskq = ((int)(half << (31 - (bbq & 31)))) >> 31;             \
                unsigned long long mmq = (unsigned long long)(long long)mskq;    \
                notS &= ~((WREG) & mmq);                                         \
            }
            STEP(w0, g + 0) STEP(w1, g + 1) STEP(w2, g + 2) STEP(w3, g + 3)
            STEP(w4, g + 4) STEP(w5, g + 5) STEP(w6, g + 6) STEP(w7, g + 7)
#undef STEP
        }
        // notS == alive set for this chunk

        // prefetch next chunk inputs (in flight during apply)
        if (chunk + 1 < NW) {
            int b2 = base + 64;
            int i0 = b2 + lane, i1 = b2 + 32 + lane;
            nd0 = (i0 < NN) ? g_mask[img][i0][chunk + 1] : 0ull;
            nd1 = (i1 < NN) ? g_mask[img][i1][chunk + 1] : 0ull;
            nv0 = (i0 < NN) ? g_svalid[img][i0] : 0;
            nv1 = (i1 < NN) ? g_svalid[img][i1] : 0;
        }

        // apply: fully-unrolled predicated loads, 4 independent accumulators.
        // (rows beyond NN have notS bit 0 -> load predicated off; lane<chunk words
        // are structurally zero -> skip.)
        if (lane >= chunk) {
            const unsigned long long* mrow = &g_mask[img][base][0];
            unsigned long long a0 = 0ull, a1 = 0ull, a2 = 0ull, a3 = 0ull;
#pragma unroll
            for (int bb = 0; bb < 64; bb += 4) {
                if ((notS >> (bb + 0)) & 1ull) a0 |= mrow[(size_t)(bb + 0) * NW + lane];
                if ((notS >> (bb + 1)) & 1ull) a1 |= mrow[(size_t)(bb + 1) * NW + lane];
                if ((notS >> (bb + 2)) & 1ull) a2 |= mrow[(size_t)(bb + 2) * NW + lane];
                if ((notS >> (bb + 3)) & 1ull) a3 |= mrow[(size_t)(bb + 3) * NW + lane];
            }
            rem |= (a0 | a1) | (a2 | a3);
        }
        __syncwarp();   // rows[] reuse guard
    }
    g_removed[img][lane] = rem;
}

// ---------------- K6: write [B,N,6] output ----------------
__global__ void k6_out(float* __restrict__ out) {
    int t = blockIdx.x * blockDim.x + threadIdx.x;
    if (t >= BB * NN) return;
    int b = t / NN, p = t % NN;
    unsigned long long w = g_removed[b][p >> 6];
    bool rem = (w >> (p & 63)) & 1ull;
    bool keep = g_svalid[b][p] && !rem;
    float* o = out + ((size_t)b * NN + p) * 6;
    if (keep) {
        float4 bx = g_obox[b][p];
        o[0] = bx.x; o[1] = bx.y; o[2] = bx.z; o[3] = bx.w;
        o[4] = g_sscore[b][p];
        o[5] = (float)g_scls[b][p];
    } else {
        o[0] = 0.f; o[1] = 0.f; o[2] = 0.f; o[3] = 0.f; o[4] = 0.f; o[5] = 0.f;
    }
}

extern "C" void kernel_launch(void* const* d_in, const int* in_sizes, int n_in,
                              void* d_out, int out_size) {
    const float* prop  = (const float*)d_in[0];
    const float* preds = (const float*)d_in[1];
    const float* bsc   = (const float*)d_in[2];
    float* out = (float*)d_out;

    (void)in_sizes; (void)n_in; (void)out_size;

    k2_sort<<<BB, 1024>>>(prop, preds, bsc);
    int tot2 = BB * NN;
    k3_gather<<<(tot2 + 255) / 256, 256>>>(prop, preds, bsc);
    dim3 mg(NB64, NB64, BB);
    k4_mask<<<mg, 64>>>();
    k5_reduce<<<BB, 32>>>();
    k6_out<<<(tot2 + 255) / 256, 256>>>(out);
}

// round 8
// speedup vs baseline: 3.1809x; 1.7017x over previous
#include <cuda_runtime.h>
#include <cstdint>

#define BB   16
#define NN   2000
#define CC   20
#define NPAD 2048
#define NW   32
#define NB64 32
#define WIMG 602.0f
#define MINB 5.0f
#define BCT  0.01f
#define CTHR 0.001f
#define IOUT 0.2f
#define MAXWH 4096.0f

__device__ unsigned long long g_keys[BB][NPAD];
__device__ float4             g_sbox[BB][NN];
__device__ float4             g_obox[BB][NN];
__device__ float              g_sarea[BB][NN];
__device__ float              g_sscore[BB][NN];
__device__ int                g_scls[BB][NN];
__device__ int                g_svalid[BB][NN];
// Padded to NPAD rows so the unconditional apply loads (rows base..base+63,
// max 2047) are always in-bounds. Rows >= NN and lower-triangular words are
// never written; __device__ globals are zero-initialized, so they OR in 0.
__device__ unsigned long long g_mask[BB][NPAD][NW];
__device__ unsigned long long g_removed[BB][NW];

__device__ __forceinline__ float neg_inf_f() { return __uint_as_float(0xff800000u); }

__device__ __forceinline__ unsigned long long make_key(
    const float* __restrict__ prop, const float* __restrict__ preds,
    const float* __restrict__ bscp, int b, int n)
{
    const float* p = prop + ((size_t)b * NN + n) * 4;
    float x1 = fminf(fmaxf(p[0], 0.f), WIMG);
    float y1 = fminf(fmaxf(p[1], 0.f), WIMG);
    float x2 = fminf(fmaxf(p[2], 0.f), WIMG);
    float y2 = fminf(fmaxf(p[3], 0.f), WIMG);

    const float* pd = preds + ((size_t)b * NN + n) * CC;
    float best = pd[0];
#pragma unroll
    for (int c = 1; c < CC; c++) { float v = pd[c]; if (v > best) best = v; }

    float bsc = bscp[b * NN + n];
    float s = bsc * best;
    bool valid = (bsc > BCT) && ((x2 - x1) >= MINB) && ((y2 - y1) >= MINB) && (s > CTHR);

    float sv = valid ? s : neg_inf_f();
    unsigned u = __float_as_uint(sv);
    u = (u & 0x80000000u) ? ~u : (u | 0x80000000u);
    return ((unsigned long long)u << 32) | (unsigned)(~(unsigned)n);
}

// ---------------- K2: key-gen + bitonic sort (descending) ----------------
__global__ void k2_sort(const float* __restrict__ prop,
                        const float* __restrict__ preds,
                        const float* __restrict__ bscp) {
    __shared__ unsigned long long s[NPAD];
    int b = blockIdx.x;
    int tid = threadIdx.x;                 // 1024 threads
    s[tid] = (tid < NN) ? make_key(prop, preds, bscp, b, tid) : 0ull;
    int t2 = tid + 1024;
    s[t2]  = (t2 < NN) ? make_key(prop, preds, bscp, b, t2) : 0ull;
    __syncthreads();
    for (int k = 2; k <= NPAD; k <<= 1) {
        for (int j = k >> 1; j > 0; j >>= 1) {
#pragma unroll
            for (int off = 0; off < 2; off++) {
                int i = tid + off * 1024;
                int ixj = i ^ j;
                if (ixj > i) {
                    unsigned long long a = s[i], c = s[ixj];
                    bool up = ((i & k) == 0);
                    bool sw = up ? (a < c) : (a > c);
                    if (sw) { s[i] = c; s[ixj] = a; }
                }
            }
            __syncthreads();
        }
    }
    g_keys[b][tid]        = s[tid];
    g_keys[b][tid + 1024] = s[tid + 1024];
}

// ---------------- K3: gather sorted per-proposal data ----------------
__global__ void k3_gather(const float* __restrict__ prop,
                          const float* __restrict__ preds,
                          const float* __restrict__ bscp) {
    int t = blockIdx.x * blockDim.x + threadIdx.x;
    if (t >= BB * NN) return;
    int b = t / NN, ppos = t % NN;
    unsigned long long key = g_keys[b][ppos];
    int n = (int)(~(unsigned)key);

    const float* p = prop + ((size_t)b * NN + n) * 4;
    float x1 = fminf(fmaxf(p[0], 0.f), WIMG);
    float y1 = fminf(fmaxf(p[1], 0.f), WIMG);
    float x2 = fminf(fmaxf(p[2], 0.f), WIMG);
    float y2 = fminf(fmaxf(p[3], 0.f), WIMG);

    const float* pd = preds + ((size_t)b * NN + n) * CC;
    float best = pd[0]; int cid = 0;
#pragma unroll
    for (int c = 1; c < CC; c++) { float v = pd[c]; if (v > best) { best = v; cid = c; } }

    float bsc = bscp[b * NN + n];
    float s = bsc * best;
    bool valid = (bsc > BCT) && ((x2 - x1) >= MINB) && ((y2 - y1) >= MINB) && (s > CTHR);

    float off = (float)cid * MAXWH;
    float ox1 = x1 + off, oy1 = y1 + off, ox2 = x2 + off, oy2 = y2 + off;

    g_sbox[b][ppos]  = make_float4(ox1, oy1, ox2, oy2);
    g_obox[b][ppos]  = make_float4(x1, y1, x2, y2);
    g_sarea[b][ppos] = fmaxf(ox2 - ox1, 0.f) * fmaxf(oy2 - oy1, 0.f);
    g_sscore[b][ppos] = s;
    g_scls[b][ppos]   = cid;
    g_svalid[b][ppos] = valid ? 1 : 0;
}

// ---------------- K4: pairwise IoU mask (upper-triangular, div-free) ----------------
__device__ __forceinline__ unsigned long long iou_bits(
    float4 bi, float ai, const float4* cbx, const float* car, int jlo, int jmax)
{
    unsigned long long m = 0ull;
#pragma unroll 4
    for (int jj = jlo; jj < jmax; jj++) {
        float4 bj = cbx[jj];
        float lx = fmaxf(bi.x, bj.x), ly = fmaxf(bi.y, bj.y);
        float rx = fminf(bi.z, bj.z), ry = fminf(bi.w, bj.w);
        float w = fmaxf(rx - lx, 0.f), h = fmaxf(ry - ly, 0.f);
        float inter = w * h;
        float uni = fmaxf(ai + car[jj] - inter, 1e-9f);
        if (fmaf(-IOUT, uni, inter) > 0.f) m |= (1ull << jj);  // iou>thr, no div
    }
    return m;
}

__global__ void k4_mask() {
    int b  = blockIdx.z;
    int rb = blockIdx.y;
    int cb = blockIdx.x;
    if (cb < rb) return;
    __shared__ float4 cbx[64];
    __shared__ float  car[64];
    int j = cb * 64 + threadIdx.x;
    if (j < NN) { cbx[threadIdx.x] = g_sbox[b][j]; car[threadIdx.x] = g_sarea[b][j]; }
    else        { cbx[threadIdx.x] = make_float4(0.f,0.f,0.f,0.f); car[threadIdx.x] = 0.f; }
    __syncthreads();

    int i = rb * 64 + threadIdx.x;
    if (i >= NN) return;
    float4 bi = g_sbox[b][i];
    float  ai = g_sarea[b][i];
    int jmax = min(64, NN - cb * 64);
    unsigned long long m;
    if (cb == rb) m = iou_bits(bi, ai, cbx, car, threadIdx.x + 1, jmax);
    else          m = iou_bits(bi, ai, cbx, car, 0, jmax);
    g_mask[b][i][cb] = m;
}

// ---------------- K5: greedy scan — register chain + branchless high-MLP apply ----------------
__global__ void __launch_bounds__(32) k5_reduce() {
    const unsigned FULL = 0xffffffffu;
    __shared__ unsigned long long rows[64];
    int img = blockIdx.x;
    int lane = threadIdx.x;
    unsigned long long rem = 0ull;

    // preload chunk 0 inputs
    unsigned long long nd0 = g_mask[img][lane][0];
    unsigned long long nd1 = g_mask[img][32 + lane][0];
    int nv0 = g_svalid[img][lane];
    int nv1 = g_svalid[img][32 + lane];

    for (int chunk = 0; chunk < NW; chunk++) {
        int base = chunk * 64;

        rows[lane]      = nd0;
        rows[lane + 32] = nd1;
        int v0 = nv0, v1 = nv1;
        __syncwarp();

        unsigned long long cur0 = __shfl_sync(FULL, rem, chunk);
        unsigned lo = __ballot_sync(FULL, v0 != 0);
        unsigned hi = __ballot_sync(FULL, v1 != 0);
        unsigned long long notS = ((((unsigned long long)hi << 32) | lo)) & ~cur0;

        // serial resolve: groups of 8 explicit LDS (off-chain), chain = shifts+LOP3
#pragma unroll
        for (int g = 0; g < 64; g += 8) {
            unsigned long long w0 = rows[g + 0], w1 = rows[g + 1];
            unsigned long long w2 = rows[g + 2], w3 = rows[g + 3];
            unsigned long long w4 = rows[g + 4], w5 = rows[g + 5];
            unsigned long long w6 = rows[g + 6], w7 = rows[g + 7];
#define STEP(WREG, BBC)                                                          \
            {                                                                    \
                const int bbq = (BBC);                                           \
                unsigned half = (bbq < 32) ? (unsigned)notS                      \
                                           : (unsigned)(notS >> 32);             \
                int mskq = ((int)(half << (31 - (bbq & 31)))) >> 31;             \
                unsigned long long mmq = (unsigned long long)(long long)mskq;    \
                notS &= ~((WREG) & mmq);                                         \
            }
            STEP(w0, g + 0) STEP(w1, g + 1) STEP(w2, g + 2) STEP(w3, g + 3)
            STEP(w4, g + 4) STEP(w5, g + 5) STEP(w6, g + 6) STEP(w7, g + 7)
#undef STEP
        }
        // notS == alive set for this chunk

        // prefetch next chunk inputs (in flight during apply)
        if (chunk + 1 < NW) {
            int b2 = base + 64;
            int i0 = b2 + lane, i1 = b2 + 32 + lane;
            nd0 = g_mask[img][i0][chunk + 1];          // padded rows: in-bounds, zero
            nd1 = g_mask[img][i1][chunk + 1];
            nv0 = (i0 < NN) ? g_svalid[img][i0] : 0;
            nv1 = (i1 < NN) ? g_svalid[img][i1] : 0;
        }

        // apply: branchless — unconditional loads in blocks of 16 (all in flight),
        // AND with sign-extended alive-bit mask. Padding rows / lower-triangular
        // words are zero-initialized device memory (never written) -> OR 0.
        {
            const unsigned long long* mrow = &g_mask[img][base][0];
            unsigned long long a0 = 0ull, a1 = 0ull, a2 = 0ull, a3 = 0ull;
#pragma unroll
            for (int g = 0; g < 64; g += 16) {
                unsigned long long t0  = mrow[(g + 0)  * NW + lane];
                unsigned long long t1  = mrow[(g + 1)  * NW + lane];
                unsigned long long t2  = mrow[(g + 2)  * NW + lane];
                unsigned long long t3  = mrow[(g + 3)  * NW + lane];
                unsigned long long t4  = mrow[(g + 4)  * NW + lane];
                unsigned long long t5  = mrow[(g + 5)  * NW + lane];
                unsigned long long t6  = mrow[(g + 6)  * NW + lane];
                unsigned long long t7  = mrow[(g + 7)  * NW + lane];
                unsigned long long t8  = mrow[(g + 8)  * NW + lane];
                unsigned long long t9  = mrow[(g + 9)  * NW + lane];
                unsigned long long t10 = mrow[(g + 10) * NW + lane];
                unsigned long long t11 = mrow[(g + 11) * NW + lane];
                unsigned long long t12 = mrow[(g + 12) * NW + lane];
                unsigned long long t13 = mrow[(g + 13) * NW + lane];
                unsigned long long t14 = mrow[(g + 14) * NW + lane];
                unsigned long long t15 = mrow[(g + 15) * NW + lane];
#define BM(K) ((unsigned long long)(-(long long)((notS >> (g + (K))) & 1ull)))
                a0 |= t0  & BM(0);   a1 |= t1  & BM(1);
                a2 |= t2  & BM(2);   a3 |= t3  & BM(3);
                a0 |= t4  & BM(4);   a1 |= t5  & BM(5);
                a2 |= t6  & BM(6);   a3 |= t7  & BM(7);
                a0 |= t8  & BM(8);   a1 |= t9  & BM(9);
                a2 |= t10 & BM(10);  a3 |= t11 & BM(11);
                a0 |= t12 & BM(12);  a1 |= t13 & BM(13);
                a2 |= t14 & BM(14);  a3 |= t15 & BM(15);
#undef BM
            }
            rem |= (a0 | a1) | (a2 | a3);
        }
        __syncwarp();   // rows[] reuse guard
    }
    g_removed[img][lane] = rem;
}

// ---------------- K6: write [B,N,6] output ----------------
__global__ void k6_out(float* __restrict__ out) {
    int t = blockIdx.x * blockDim.x + threadIdx.x;
    if (t >= BB * NN) return;
    int b = t / NN, p = t % NN;
    unsigned long long w = g_removed[b][p >> 6];
    bool rem = (w >> (p & 63)) & 1ull;
    bool keep = g_svalid[b][p] && !rem;
    float* o = out + ((size_t)b * NN + p) * 6;
    if (keep) {
        float4 bx = g_obox[b][p];
        o[0] = bx.x; o[1] = bx.y; o[2] = bx.z; o[3] = bx.w;
        o[4] = g_sscore[b][p];
        o[5] = (float)g_scls[b][p];
    } else {
        o[0] = 0.f; o[1] = 0.f; o[2] = 0.f; o[3] = 0.f; o[4] = 0.f; o[5] = 0.f;
    }
}

extern "C" void kernel_launch(void* const* d_in, const int* in_sizes, int n_in,
                              void* d_out, int out_size) {
    const float* prop  = (const float*)d_in[0];
    const float* preds = (const float*)d_in[1];
    const float* bsc   = (const float*)d_in[2];
    float* out = (float*)d_out;

    (void)in_sizes; (void)n_in; (void)out_size;

    k2_sort<<<BB, 1024>>>(prop, preds, bsc);
    int tot2 = BB * NN;
    k3_gather<<<(tot2 + 255) / 256, 256>>>(prop, preds, bsc);
    dim3 mg(NB64, NB64, BB);
    k4_mask<<<mg, 64>>>();
    k5_reduce<<<BB, 32>>>();
    k6_out<<<(tot2 + 255) / 256, 256>>>(out);
}

// round 9
// speedup vs baseline: 4.1501x; 1.3047x over previous
#include <cuda_runtime.h>
#include <cstdint>

#define BB   16
#define NN   2000
#define CC   20
#define NPAD 2048
#define NW   32
#define NB64 32
#define WIMG 602.0f
#define MINB 5.0f
#define BCT  0.01f
#define CTHR 0.001f
#define IOUT 0.2f
#define MAXWH 4096.0f

__device__ unsigned long long g_keys[BB][NPAD];
__device__ float4             g_sbox[BB][NN];
__device__ float4             g_obox[BB][NN];
__device__ float              g_sarea[BB][NN];
__device__ float              g_sscore[BB][NN];
__device__ int                g_scls[BB][NN];
__device__ int                g_svalid[BB][NN];
// Padded to NPAD rows: unconditional loads on rows base..base+63 stay in-bounds.
// Rows >= NN and lower-triangular words are never written; __device__ globals
// are zero-initialized, so they OR in 0.
__device__ unsigned long long g_mask[BB][NPAD][NW];
__device__ unsigned long long g_removed[BB][NW];

__device__ __forceinline__ float neg_inf_f() { return __uint_as_float(0xff800000u); }

__device__ __forceinline__ unsigned long long make_key(
    const float* __restrict__ prop, const float* __restrict__ preds,
    const float* __restrict__ bscp, int b, int n)
{
    const float* p = prop + ((size_t)b * NN + n) * 4;
    float x1 = fminf(fmaxf(p[0], 0.f), WIMG);
    float y1 = fminf(fmaxf(p[1], 0.f), WIMG);
    float x2 = fminf(fmaxf(p[2], 0.f), WIMG);
    float y2 = fminf(fmaxf(p[3], 0.f), WIMG);

    const float* pd = preds + ((size_t)b * NN + n) * CC;
    float best = pd[0];
#pragma unroll
    for (int c = 1; c < CC; c++) { float v = pd[c]; if (v > best) best = v; }

    float bsc = bscp[b * NN + n];
    float s = bsc * best;
    bool valid = (bsc > BCT) && ((x2 - x1) >= MINB) && ((y2 - y1) >= MINB) && (s > CTHR);

    float sv = valid ? s : neg_inf_f();
    unsigned u = __float_as_uint(sv);
    u = (u & 0x80000000u) ? ~u : (u | 0x80000000u);
    return ((unsigned long long)u << 32) | (unsigned)(~(unsigned)n);
}

// ---------------- K2: key-gen + bitonic sort (descending) ----------------
__global__ void k2_sort(const float* __restrict__ prop,
                        const float* __restrict__ preds,
                        const float* __restrict__ bscp) {
    __shared__ unsigned long long s[NPAD];
    int b = blockIdx.x;
    int tid = threadIdx.x;                 // 1024 threads
    s[tid] = (tid < NN) ? make_key(prop, preds, bscp, b, tid) : 0ull;
    int t2 = tid + 1024;
    s[t2]  = (t2 < NN) ? make_key(prop, preds, bscp, b, t2) : 0ull;
    __syncthreads();
    for (int k = 2; k <= NPAD; k <<= 1) {
        for (int j = k >> 1; j > 0; j >>= 1) {
#pragma unroll
            for (int off = 0; off < 2; off++) {
                int i = tid + off * 1024;
                int ixj = i ^ j;
                if (ixj > i) {
                    unsigned long long a = s[i], c = s[ixj];
                    bool up = ((i & k) == 0);
                    bool sw = up ? (a < c) : (a > c);
                    if (sw) { s[i] = c; s[ixj] = a; }
                }
            }
            __syncthreads();
        }
    }
    g_keys[b][tid]        = s[tid];
    g_keys[b][tid + 1024] = s[tid + 1024];
}

// ---------------- K3: gather sorted per-proposal data ----------------
__global__ void k3_gather(const float* __restrict__ prop,
                          const float* __restrict__ preds,
                          const float* __restrict__ bscp) {
    int t = blockIdx.x * blockDim.x + threadIdx.x;
    if (t >= BB * NN) return;
    int b = t / NN, ppos = t % NN;
    unsigned long long key = g_keys[b][ppos];
    int n = (int)(~(unsigned)key);

    const float* p = prop + ((size_t)b * NN + n) * 4;
    float x1 = fminf(fmaxf(p[0], 0.f), WIMG);
    float y1 = fminf(fmaxf(p[1], 0.f), WIMG);
    float x2 = fminf(fmaxf(p[2], 0.f), WIMG);
    float y2 = fminf(fmaxf(p[3], 0.f), WIMG);

    const float* pd = preds + ((size_t)b * NN + n) * CC;
    float best = pd[0]; int cid = 0;
#pragma unroll
    for (int c = 1; c < CC; c++) { float v = pd[c]; if (v > best) { best = v; cid = c; } }

    float bsc = bscp[b * NN + n];
    float s = bsc * best;
    bool valid = (bsc > BCT) && ((x2 - x1) >= MINB) && ((y2 - y1) >= MINB) && (s > CTHR);

    float off = (float)cid * MAXWH;
    float ox1 = x1 + off, oy1 = y1 + off, ox2 = x2 + off, oy2 = y2 + off;

    g_sbox[b][ppos]  = make_float4(ox1, oy1, ox2, oy2);
    g_obox[b][ppos]  = make_float4(x1, y1, x2, y2);
    g_sarea[b][ppos] = fmaxf(ox2 - ox1, 0.f) * fmaxf(oy2 - oy1, 0.f);
    g_sscore[b][ppos] = s;
    g_scls[b][ppos]   = cid;
    g_svalid[b][ppos] = valid ? 1 : 0;
}

// ---------------- K4: pairwise IoU mask (upper-triangular, div-free) ----------------
__device__ __forceinline__ unsigned long long iou_bits(
    float4 bi, float ai, const float4* cbx, const float* car, int jlo, int jmax)
{
    unsigned long long m = 0ull;
#pragma unroll 4
    for (int jj = jlo; jj < jmax; jj++) {
        float4 bj = cbx[jj];
        float lx = fmaxf(bi.x, bj.x), ly = fmaxf(bi.y, bj.y);
        float rx = fminf(bi.z, bj.z), ry = fminf(bi.w, bj.w);
        float w = fmaxf(rx - lx, 0.f), h = fmaxf(ry - ly, 0.f);
        float inter = w * h;
        float uni = fmaxf(ai + car[jj] - inter, 1e-9f);
        if (fmaf(-IOUT, uni, inter) > 0.f) m |= (1ull << jj);  // iou>thr, no div
    }
    return m;
}

__global__ void k4_mask() {
    int b  = blockIdx.z;
    int rb = blockIdx.y;
    int cb = blockIdx.x;
    if (cb < rb) return;
    __shared__ float4 cbx[64];
    __shared__ float  car[64];
    int j = cb * 64 + threadIdx.x;
    if (j < NN) { cbx[threadIdx.x] = g_sbox[b][j]; car[threadIdx.x] = g_sarea[b][j]; }
    else        { cbx[threadIdx.x] = make_float4(0.f,0.f,0.f,0.f); car[threadIdx.x] = 0.f; }
    __syncthreads();

    int i = rb * 64 + threadIdx.x;
    if (i >= NN) return;
    float4 bi = g_sbox[b][i];
    float  ai = g_sarea[b][i];
    int jmax = min(64, NN - cb * 64);
    unsigned long long m;
    if (cb == rb) m = iou_bits(bi, ai, cbx, car, threadIdx.x + 1, jmax);
    else          m = iou_bits(bi, ai, cbx, car, 0, jmax);
    g_mask[b][i][cb] = m;
}

// ---------------- K5: greedy scan — warp-0 resolve + 8-warp parallel apply ----------------
__global__ void __launch_bounds__(256) k5_reduce() {
    const unsigned FULL = 0xffffffffu;
    __shared__ unsigned long long rowsA[64], rowsB[64];   // diag-word double buffer
    __shared__ unsigned long long vw[NW];                 // validity words per chunk
    __shared__ unsigned long long notS_sh;
    __shared__ unsigned long long part[8];                // per-warp partial column word
    __shared__ unsigned long long allrem[8][32];

    int img = threadIdx.y == 0 ? blockIdx.x : blockIdx.x; // (keep simple)
    img = blockIdx.x;
    int tid = threadIdx.x;
    int w = tid >> 5, lane = tid & 31;

    // precompute validity words (warp w handles chunks w, w+8, w+16, w+24)
    for (int cc = w; cc < NW; cc += 8) {
        int i0 = cc * 64 + lane, i1 = i0 + 32;
        int v0 = (i0 < NN) ? g_svalid[img][i0] : 0;
        int v1 = (i1 < NN) ? g_svalid[img][i1] : 0;
        unsigned lo = __ballot_sync(FULL, v0 != 0);
        unsigned hi = __ballot_sync(FULL, v1 != 0);
        if (lane == 0) vw[cc] = ((unsigned long long)hi << 32) | lo;
    }
    // prefetch chunk 0 diagonal words
    if (tid < 64) rowsA[tid] = g_mask[img][tid][0];

    unsigned long long remp = 0ull;   // this warp's partial rem, lane = column word
    __syncthreads();

    for (int c = 0; c < NW; c++) {
        unsigned long long* rows_cur = (c & 1) ? rowsB : rowsA;
        unsigned long long* rows_nxt = (c & 1) ? rowsA : rowsB;

        // publish each warp's partial word for column c
        unsigned long long mycol = __shfl_sync(FULL, remp, c);
        if (lane == 0) part[w] = mycol;
        __syncthreads();

        if (w == 0) {
            unsigned long long cur0 = (part[0] | part[1]) | (part[2] | part[3])
                                    | (part[4] | part[5]) | (part[6] | part[7]);
            unsigned long long notS = vw[c] & ~cur0;
            // serial resolve with group-of-8 skip (uniform branch; all lanes identical)
#pragma unroll
            for (int g = 0; g < 64; g += 8) {
                unsigned long long w0 = rows_cur[g + 0], w1 = rows_cur[g + 1];
                unsigned long long w2 = rows_cur[g + 2], w3 = rows_cur[g + 3];
                unsigned long long w4 = rows_cur[g + 4], w5 = rows_cur[g + 5];
                unsigned long long w6 = rows_cur[g + 6], w7 = rows_cur[g + 7];
                if (((w0 | w1) | (w2 | w3) | ((w4 | w5) | (w6 | w7))) != 0ull) {
#define STEP(WREG, BBC)                                                          \
                    {                                                            \
                        const int bbq = (BBC);                                   \
                        unsigned half = (bbq < 32) ? (unsigned)notS              \
                                                   : (unsigned)(notS >> 32);    \
                        int mskq = ((int)(half << (31 - (bbq & 31)))) >> 31;     \
                        unsigned long long mmq =                                 \
                            (unsigned long long)(long long)mskq;                 \
                        notS &= ~((WREG) & mmq);                                 \
                    }
                    STEP(w0, g + 0) STEP(w1, g + 1) STEP(w2, g + 2) STEP(w3, g + 3)
                    STEP(w4, g + 4) STEP(w5, g + 5) STEP(w6, g + 6) STEP(w7, g + 7)
#undef STEP
                }
            }
            if (lane == 0) notS_sh = notS;
        } else if (w == 1 || w == 2) {
            // prefetch next chunk's diagonal words while warp 0 resolves
            if (c + 1 < NW) {
                int r = (w - 1) * 32 + lane;                  // 0..63
                rows_nxt[r] = g_mask[img][(c + 1) * 64 + r][c + 1];
            }
        }
        __syncthreads();
        unsigned long long notS = notS_sh;

        // apply: warp w owns rows c*64 + w*8 .. +7; 8 unconditional loads in flight
        {
            const unsigned long long* mrow = &g_mask[img][c * 64 + w * 8][0];
            unsigned long long t0 = mrow[0 * NW + lane];
            unsigned long long t1 = mrow[1 * NW + lane];
            unsigned long long t2 = mrow[2 * NW + lane];
            unsigned long long t3 = mrow[3 * NW + lane];
            unsigned long long t4 = mrow[4 * NW + lane];
            unsigned long long t5 = mrow[5 * NW + lane];
            unsigned long long t6 = mrow[6 * NW + lane];
            unsigned long long t7 = mrow[7 * NW + lane];
            int rb0 = w * 8;
#define BM(K) ((unsigned long long)(-(long long)((notS >> (rb0 + (K))) & 1ull)))
            unsigned long long a0 = (t0 & BM(0)) | (t1 & BM(1));
            unsigned long long a1 = (t2 & BM(2)) | (t3 & BM(3));
            unsigned long long a2 = (t4 & BM(4)) | (t5 & BM(5));
            unsigned long long a3 = (t6 & BM(6)) | (t7 & BM(7));
#undef BM
            remp |= (a0 | a1) | (a2 | a3);
        }
        // loop-top __syncthreads (after part write) orders rem reads vs part writes
    }

    // final reduction: OR the 8 warps' partial rems per column
    allrem[w][lane] = remp;
    __syncthreads();
    if (w == 0) {
        unsigned long long tot = (allrem[0][lane] | allrem[1][lane])
                               | (allrem[2][lane] | allrem[3][lane])
                               | ((allrem[4][lane] | allrem[5][lane])
                               |  (allrem[6][lane] | allrem[7][lane]));
        g_removed[img][lane] = tot;
    }
}

// ---------------- K6: write [B,N,6] output ----------------
__global__ void k6_out(float* __restrict__ out) {
    int t = blockIdx.x * blockDim.x + threadIdx.x;
    if (t >= BB * NN) return;
    int b = t / NN, p = t % NN;
    unsigned long long w = g_removed[b][p >> 6];
    bool rem = (w >> (p & 63)) & 1ull;
    bool keep = g_svalid[b][p] && !rem;
    float* o = out + ((size_t)b * NN + p) * 6;
    if (keep) {
        float4 bx = g_obox[b][p];
        o[0] = bx.x; o[1] = bx.y; o[2] = bx.z; o[3] = bx.w;
        o[4] = g_sscore[b][p];
        o[5] = (float)g_scls[b][p];
    } else {
        o[0] = 0.f; o[1] = 0.f; o[2] = 0.f; o[3] = 0.f; o[4] = 0.f; o[5] = 0.f;
    }
}

extern "C" void kernel_launch(void* const* d_in, const int* in_sizes, int n_in,
                              void* d_out, int out_size) {
    const float* prop  = (const float*)d_in[0];
    const float* preds = (const float*)d_in[1];
    const float* bsc   = (const float*)d_in[2];
    float* out = (float*)d_out;

    (void)in_sizes; (void)n_in; (void)out_size;

    k2_sort<<<BB, 1024>>>(prop, preds, bsc);
    int tot2 = BB * NN;
    k3_gather<<<(tot2 + 255) / 256, 256>>>(prop, preds, bsc);
    dim3 mg(NB64, NB64, BB);
    k4_mask<<<mg, 64>>>();
    k5_reduce<<<BB, 256>>>();
    k6_out<<<(tot2 + 255) / 256, 256>>>(out);
}

// round 10
// speedup vs baseline: 6.1173x; 1.4740x over previous
#include <cuda_runtime.h>
#include <cstdint>

#define BB   16
#define NN   2000
#define CC   20
#define NPAD 2048
#define NW   32
#define CCAP 1024          // per-(img,class) list capacity (binomial(2000,1/20) max ~150)
#define WIMG 602.0f
#define MINB 5.0f
#define BCT  0.01f
#define CTHR 0.001f
#define IOUT 0.2f
#define MAXWH 4096.0f

__device__ unsigned long long g_keys[BB][NPAD];
__device__ float4             g_sbox[BB][NN];
__device__ float4             g_obox[BB][NN];
__device__ float              g_sarea[BB][NN];
__device__ float              g_sscore[BB][NN];
__device__ int                g_scls[BB][NN];
__device__ int                g_svalid[BB][NN];
__device__ unsigned long long g_mask[BB][NPAD][NW];   // sparse; zeroed by k0 each launch
__device__ unsigned long long g_removed[BB][NW];
__device__ int                g_ccnt[BB][CC];          // per-class counts (zeroed by k0)
__device__ int                g_clist[BB][CC][CCAP];   // per-class sorted-position lists

__device__ __forceinline__ float neg_inf_f() { return __uint_as_float(0xff800000u); }

// ---------------- K0: zero mask + class counters ----------------
__global__ void k0_zero() {
    size_t t = (size_t)blockIdx.x * blockDim.x + threadIdx.x;
    size_t stride = (size_t)gridDim.x * blockDim.x;
    unsigned long long* m = &g_mask[0][0][0];
    const size_t total = (size_t)BB * NPAD * NW;
    for (size_t i = t; i < total; i += stride) m[i] = 0ull;
    if (t < BB * CC) (&g_ccnt[0][0])[t] = 0;
}

__device__ __forceinline__ unsigned long long make_key(
    const float* __restrict__ prop, const float* __restrict__ preds,
    const float* __restrict__ bscp, int b, int n)
{
    const float* p = prop + ((size_t)b * NN + n) * 4;
    float x1 = fminf(fmaxf(p[0], 0.f), WIMG);
    float y1 = fminf(fmaxf(p[1], 0.f), WIMG);
    float x2 = fminf(fmaxf(p[2], 0.f), WIMG);
    float y2 = fminf(fmaxf(p[3], 0.f), WIMG);

    const float* pd = preds + ((size_t)b * NN + n) * CC;
    float best = pd[0];
#pragma unroll
    for (int c = 1; c < CC; c++) { float v = pd[c]; if (v > best) best = v; }

    float bsc = bscp[b * NN + n];
    float s = bsc * best;
    bool valid = (bsc > BCT) && ((x2 - x1) >= MINB) && ((y2 - y1) >= MINB) && (s > CTHR);

    float sv = valid ? s : neg_inf_f();
    unsigned u = __float_as_uint(sv);
    u = (u & 0x80000000u) ? ~u : (u | 0x80000000u);
    return ((unsigned long long)u << 32) | (unsigned)(~(unsigned)n);
}

// ---------------- K2: key-gen + bitonic sort (descending) ----------------
__global__ void k2_sort(const float* __restrict__ prop,
                        const float* __restrict__ preds,
                        const float* __restrict__ bscp) {
    __shared__ unsigned long long s[NPAD];
    int b = blockIdx.x;
    int tid = threadIdx.x;                 // 1024 threads
    s[tid] = (tid < NN) ? make_key(prop, preds, bscp, b, tid) : 0ull;
    int t2 = tid + 1024;
    s[t2]  = (t2 < NN) ? make_key(prop, preds, bscp, b, t2) : 0ull;
    __syncthreads();
    for (int k = 2; k <= NPAD; k <<= 1) {
        for (int j = k >> 1; j > 0; j >>= 1) {
#pragma unroll
            for (int off = 0; off < 2; off++) {
                int i = tid + off * 1024;
                int ixj = i ^ j;
                if (ixj > i) {
                    unsigned long long a = s[i], c = s[ixj];
                    bool up = ((i & k) == 0);
                    bool sw = up ? (a < c) : (a > c);
                    if (sw) { s[i] = c; s[ixj] = a; }
                }
            }
            __syncthreads();
        }
    }
    g_keys[b][tid]        = s[tid];
    g_keys[b][tid + 1024] = s[tid + 1024];
}

// ---------------- K3: gather + per-class compaction ----------------
__global__ void k3_gather(const float* __restrict__ prop,
                          const float* __restrict__ preds,
                          const float* __restrict__ bscp) {
    int t = blockIdx.x * blockDim.x + threadIdx.x;
    if (t >= BB * NN) return;
    int b = t / NN, ppos = t % NN;
    unsigned long long key = g_keys[b][ppos];
    int n = (int)(~(unsigned)key);

    const float* p = prop + ((size_t)b * NN + n) * 4;
    float x1 = fminf(fmaxf(p[0], 0.f), WIMG);
    float y1 = fminf(fmaxf(p[1], 0.f), WIMG);
    float x2 = fminf(fmaxf(p[2], 0.f), WIMG);
    float y2 = fminf(fmaxf(p[3], 0.f), WIMG);

    const float* pd = preds + ((size_t)b * NN + n) * CC;
    float best = pd[0]; int cid = 0;
#pragma unroll
    for (int c = 1; c < CC; c++) { float v = pd[c]; if (v > best) { best = v; cid = c; } }

    float bsc = bscp[b * NN + n];
    float s = bsc * best;
    bool valid = (bsc > BCT) && ((x2 - x1) >= MINB) && ((y2 - y1) >= MINB) && (s > CTHR);

    float off = (float)cid * MAXWH;
    float ox1 = x1 + off, oy1 = y1 + off, ox2 = x2 + off, oy2 = y2 + off;

    g_sbox[b][ppos]  = make_float4(ox1, oy1, ox2, oy2);
    g_obox[b][ppos]  = make_float4(x1, y1, x2, y2);
    g_sarea[b][ppos] = fmaxf(ox2 - ox1, 0.f) * fmaxf(oy2 - oy1, 0.f);
    g_sscore[b][ppos] = s;
    g_scls[b][ppos]   = cid;
    g_svalid[b][ppos] = valid ? 1 : 0;

    int slot = atomicAdd(&g_ccnt[b][cid], 1);
    if (slot < CCAP) g_clist[b][cid][slot] = ppos;
}

// ---------------- K4: per-class pairwise IoU -> sparse suppression bits ----------------
// Cross-class pairs are provably IoU==0 (class offsets differ by >= 4096 > image
// extent, so the clamped intersection is exactly 0), so only same-class pairs
// are computed. Bits are atomicOr'd (order-independent -> deterministic).
__global__ void __launch_bounds__(256) k4_cls() {
    __shared__ float4 sb[CCAP];
    __shared__ float  sa[CCAP];
    __shared__ unsigned short sp[CCAP];
    int img = blockIdx.y, cls = blockIdx.x;
    int n = g_ccnt[img][cls];
    if (n > CCAP) n = CCAP;
    for (int i = threadIdx.x; i < n; i += blockDim.x) {
        int p = g_clist[img][cls][i];
        sb[i] = g_sbox[img][p];
        sa[i] = g_sarea[img][p];
        sp[i] = (unsigned short)p;
    }
    __syncthreads();
    for (int a = threadIdx.x; a < n; a += blockDim.x) {
        float4 ba = sb[a];
        float  aa = sa[a];
        int    pa = sp[a];
        for (int b2 = a + 1; b2 < n; b2++) {
            float4 bb = sb[b2];
            float lx = fmaxf(ba.x, bb.x), ly = fmaxf(ba.y, bb.y);
            float rx = fminf(ba.z, bb.z), ry = fminf(ba.w, bb.w);
            float w = fmaxf(rx - lx, 0.f), h = fmaxf(ry - ly, 0.f);
            float inter = w * h;
            float uni = fmaxf(aa + sa[b2] - inter, 1e-9f);
            if (fmaf(-IOUT, uni, inter) > 0.f) {
                int pb = sp[b2];
                int i = min(pa, pb), j = max(pa, pb);
                atomicOr(&g_mask[img][i][j >> 6], 1ull << (j & 63));
            }
        }
    }
}

// ---------------- K5: greedy scan — prefetched apply + flag-skipped resolve ----------------
__global__ void __launch_bounds__(256) k5_reduce() {
    const unsigned FULL = 0xffffffffu;
    __shared__ unsigned long long rowsA[64], rowsB[64];
    __shared__ int gflagA[8], gflagB[8];
    __shared__ unsigned long long vw[NW];
    __shared__ unsigned long long notS_sh;
    __shared__ unsigned long long part[8];
    __shared__ unsigned long long allrem[8][32];

    int img = blockIdx.x;
    int tid = threadIdx.x;
    int w = tid >> 5, lane = tid & 31;

    // validity words (warp w handles chunks w, w+8, ...)
    for (int cc = w; cc < NW; cc += 8) {
        int i0 = cc * 64 + lane, i1 = i0 + 32;
        int v0 = (i0 < NN) ? g_svalid[img][i0] : 0;
        int v1 = (i1 < NN) ? g_svalid[img][i1] : 0;
        unsigned lo = __ballot_sync(FULL, v0 != 0);
        unsigned hi = __ballot_sync(FULL, v1 != 0);
        if (lane == 0) vw[cc] = ((unsigned long long)hi << 32) | lo;
    }
    // chunk 0 diagonal words
    if (tid < 64) rowsA[tid] = g_mask[img][tid][0];
    __syncthreads();
    if (tid < 8) {
        unsigned long long o = rowsA[tid * 8 + 0] | rowsA[tid * 8 + 1]
                             | rowsA[tid * 8 + 2] | rowsA[tid * 8 + 3]
                             | rowsA[tid * 8 + 4] | rowsA[tid * 8 + 5]
                             | rowsA[tid * 8 + 6] | rowsA[tid * 8 + 7];
        gflagA[tid] = (o != 0ull);
    }

    // prefetch chunk-0 apply rows (warp w owns rows w*8..w*8+7; lane = column word)
    unsigned long long t0, t1, t2, t3, t4, t5, t6, t7;
    {
        const unsigned long long* mrow = &g_mask[img][w * 8][0];
        t0 = mrow[0 * NW + lane]; t1 = mrow[1 * NW + lane];
        t2 = mrow[2 * NW + lane]; t3 = mrow[3 * NW + lane];
        t4 = mrow[4 * NW + lane]; t5 = mrow[5 * NW + lane];
        t6 = mrow[6 * NW + lane]; t7 = mrow[7 * NW + lane];
    }
    unsigned long long remp = 0ull;
    __syncthreads();

    for (int c = 0; c < NW; c++) {
        unsigned long long* rows_cur = (c & 1) ? rowsB : rowsA;
        unsigned long long* rows_nxt = (c & 1) ? rowsA : rowsB;
        int* gf_cur = (c & 1) ? gflagB : gflagA;
        int* gf_nxt = (c & 1) ? gflagA : gflagB;

        unsigned long long mycol = __shfl_sync(FULL, remp, c);
        if (lane == 0) part[w] = mycol;
        __syncthreads();

        if (w == 0) {
            unsigned long long cur0 = (part[0] | part[1]) | (part[2] | part[3])
                                    | (part[4] | part[5]) | (part[6] | part[7]);
            unsigned long long notS = vw[c] & ~cur0;
#pragma unroll
            for (int g = 0; g < 64; g += 8) {
                if (gf_cur[g >> 3]) {
                    unsigned long long w0 = rows_cur[g + 0], w1 = rows_cur[g + 1];
                    unsigned long long w2 = rows_cur[g + 2], w3 = rows_cur[g + 3];
                    unsigned long long w4 = rows_cur[g + 4], w5 = rows_cur[g + 5];
                    unsigned long long w6 = rows_cur[g + 6], w7 = rows_cur[g + 7];
#define STEP(WREG, BBC)                                                          \
                    {                                                            \
                        const int bbq = (BBC);                                   \
                        unsigned half = (bbq < 32) ? (unsigned)notS              \
                                                   : (unsigned)(notS >> 32);    \
                        int mskq = ((int)(half << (31 - (bbq & 31)))) >> 31;     \
                        unsigned long long mmq =                                 \
                            (unsigned long long)(long long)mskq;                 \
                        notS &= ~((WREG) & mmq);                                 \
                    }
                    STEP(w0, g + 0) STEP(w1, g + 1) STEP(w2, g + 2) STEP(w3, g + 3)
                    STEP(w4, g + 4) STEP(w5, g + 5) STEP(w6, g + 6) STEP(w7, g + 7)
#undef STEP
                }
            }
            if (lane == 0) notS_sh = notS;
        } else if ((w == 1 || w == 2) && (c + 1 < NW)) {
            // prefetch next chunk's diagonal words + group flags
            int r = (w - 1) * 32 + lane;
            unsigned long long v = g_mask[img][(c + 1) * 64 + r][c + 1];
            rows_nxt[r] = v;
            unsigned long long o = v;
            o |= __shfl_xor_sync(FULL, o, 1);
            o |= __shfl_xor_sync(FULL, o, 2);
            o |= __shfl_xor_sync(FULL, o, 4);
            if ((lane & 7) == 0) gf_nxt[r >> 3] = (o != 0ull);
        }
        __syncthreads();
        unsigned long long notS = notS_sh;

        // apply: pure ALU on prefetched registers
        {
            int rb0 = w * 8;
#define BM(K) ((unsigned long long)(-(long long)((notS >> (rb0 + (K))) & 1ull)))
            unsigned long long a0 = (t0 & BM(0)) | (t1 & BM(1));
            unsigned long long a1 = (t2 & BM(2)) | (t3 & BM(3));
            unsigned long long a2 = (t4 & BM(4)) | (t5 & BM(5));
            unsigned long long a3 = (t6 & BM(6)) | (t7 & BM(7));
#undef BM
            remp |= (a0 | a1) | (a2 | a3);
        }
        // prefetch next chunk's apply rows (in flight across next boundary)
        if (c + 1 < NW) {
            const unsigned long long* mrow = &g_mask[img][(c + 1) * 64 + w * 8][0];
            t0 = mrow[0 * NW + lane]; t1 = mrow[1 * NW + lane];
            t2 = mrow[2 * NW + lane]; t3 = mrow[3 * NW + lane];
            t4 = mrow[4 * NW + lane]; t5 = mrow[5 * NW + lane];
            t6 = mrow[6 * NW + lane]; t7 = mrow[7 * NW + lane];
        }
    }

    allrem[w][lane] = remp;
    __syncthreads();
    if (w == 0) {
        unsigned long long tot = (allrem[0][lane] | allrem[1][lane])
                               | (allrem[2][lane] | allrem[3][lane])
                               | ((allrem[4][lane] | allrem[5][lane])
                               |  (allrem[6][lane] | allrem[7][lane]));
        g_removed[img][lane] = tot;
    }
}

// ---------------- K6: write [B,N,6] output ----------------
__global__ void k6_out(float* __restrict__ out) {
    int t = blockIdx.x * blockDim.x + threadIdx.x;
    if (t >= BB * NN) return;
    int b = t / NN, p = t % NN;
    unsigned long long w = g_removed[b][p >> 6];
    bool rem = (w >> (p & 63)) & 1ull;
    bool keep = g_svalid[b][p] && !rem;
    float* o = out + ((size_t)b * NN + p) * 6;
    if (keep) {
        float4 bx = g_obox[b][p];
        o[0] = bx.x; o[1] = bx.y; o[2] = bx.z; o[3] = bx.w;
        o[4] = g_sscore[b][p];
        o[5] = (float)g_scls[b][p];
    } else {
        o[0] = 0.f; o[1] = 0.f; o[2] = 0.f; o[3] = 0.f; o[4] = 0.f; o[5] = 0.f;
    }
}

extern "C" void kernel_launch(void* const* d_in, const int* in_sizes, int n_in,
                              void* d_out, int out_size) {
    const float* prop  = (const float*)d_in[0];
    const float* preds = (const float*)d_in[1];
    const float* bsc   = (const float*)d_in[2];
    float* out = (float*)d_out;

    (void)in_sizes; (void)n_in; (void)out_size;

    k0_zero<<<1024, 256>>>();
    k2_sort<<<BB, 1024>>>(prop, preds, bsc);
    int tot2 = BB * NN;
    k3_gather<<<(tot2 + 255) / 256, 256>>>(prop, preds, bsc);
    dim3 cg(CC, BB);
    k4_cls<<<cg, 256>>>();
    k5_reduce<<<BB, 256>>>();
    k6_out<<<(tot2 + 255) / 256, 256>>>(out);
}